// round 3
// baseline (speedup 1.0000x reference)
#include <cuda_runtime.h>

#define NN   20000
#define EG   200000
#define ELG  400000
#define HD   256
#define HD2  512
#define NL   4
#define NG   128

// ---------------- scratch (device globals; no allocations allowed) ----------------
__device__ float  g_hnode[NN * HD];
__device__ float  g_P[NN * HD];
__device__ float  g_Q[NN * HD];
__device__ float  g_h[EG * HD];        // current layer state (pre-BN)
__device__ float  g_hmid[EG * HD];     // x + aggr
__device__ float  g_mid2[EG * HD2];    // MLP hidden
__device__ float4 g_nbg[EG];           // edge_dist_basis @ Wg_nb + bg_nb
__device__ float4 g_ebg[ELG];          // edge_attr_lg  @ Wg_eb + bg_eb
__device__ int    g_counts_lg[EG];
__device__ int    g_counts_g[NN];
__device__ int    g_rowptr_lg[EG + 1];
__device__ int    g_rowptr_g[NN + 1];
__device__ int    g_cursor_lg[EG];
__device__ int    g_cursor_g[NN];
__device__ int    g_src_sorted[ELG];
__device__ float4 g_nbg_sorted[ELG];
__device__ float4 g_ebg_sorted[ELG];
__device__ int    g_eid_sorted[EG];
__device__ double g_bnsum[HD];
__device__ double g_bnsq[HD];
__device__ float  g_bnscale[HD];
__device__ float  g_bnshift[HD];
__device__ float  g_gsum[NG * HD];
__device__ int    g_cnt[NG];

// ---------------- setup / zero ----------------
__global__ void k_zero_setup() {
    int i = blockIdx.x * 256 + threadIdx.x;
    if (i < EG)       g_counts_lg[i] = 0;
    if (i < NN)       g_counts_g[i] = 0;
    if (i < NG * HD)  g_gsum[i] = 0.f;
    if (i < NG)       g_cnt[i] = 0;
}

__global__ void k_zero_bn() {
    int f = threadIdx.x;
    g_bnsum[f] = 0.0;
    g_bnsq[f] = 0.0;
}

// ---------------- histograms ----------------
__global__ void k_hist_lg(const int* __restrict__ eilg) {
    int e = blockIdx.x * 256 + threadIdx.x;
    if (e < ELG) atomicAdd(&g_counts_lg[eilg[ELG + e]], 1);
}
__global__ void k_hist_g(const int* __restrict__ eig) {
    int e = blockIdx.x * 256 + threadIdx.x;
    if (e < EG) atomicAdd(&g_counts_g[eig[EG + e]], 1);
}
__global__ void k_hist_batch(const int* __restrict__ bv) {
    int n = blockIdx.x * 256 + threadIdx.x;
    if (n < NN) atomicAdd(&g_cnt[bv[n]], 1);
}

// ---------------- exclusive scan (single block, 1024 threads) ----------------
__global__ void k_scan(int which) {
    const int* in;
    int* out;
    int n;
    if (which == 0) { in = g_counts_lg; out = g_rowptr_lg; n = EG; }
    else            { in = g_counts_g;  out = g_rowptr_g;  n = NN; }
    __shared__ int sd[1024];
    int t = threadIdx.x;
    int carry = 0;
    for (int base = 0; base < n; base += 1024) {
        int v = (base + t < n) ? in[base + t] : 0;
        sd[t] = v;
        __syncthreads();
        #pragma unroll
        for (int off = 1; off < 1024; off <<= 1) {
            int x = (t >= off) ? sd[t - off] : 0;
            __syncthreads();
            sd[t] += x;
            __syncthreads();
        }
        int incl = sd[t];
        int tot = sd[1023];
        if (base + t < n) out[base + t] = carry + incl - v;
        carry += tot;
        __syncthreads();
    }
    if (t == 0) out[n] = carry;
}

__global__ void k_prepcur() {
    int i = blockIdx.x * 256 + threadIdx.x;
    if (i < EG) g_cursor_lg[i] = g_rowptr_lg[i];
    if (i < NN) g_cursor_g[i] = g_rowptr_g[i];
}

// ---------------- tiny 4->4 basis projections ----------------
__global__ void k_basis(const float* __restrict__ in, const float* __restrict__ W,
                        const float* __restrict__ b, int which) {
    int R = (which == 0) ? EG : ELG;
    float4* out = (which == 0) ? g_nbg : g_ebg;
    int r = blockIdx.x * 256 + threadIdx.x;
    if (r >= R) return;
    float4 v = ((const float4*)in)[r];
    float4 o;
    o.x = v.x * W[0] + v.y * W[4] + v.z * W[8]  + v.w * W[12] + b[0];
    o.y = v.x * W[1] + v.y * W[5] + v.z * W[9]  + v.w * W[13] + b[1];
    o.z = v.x * W[2] + v.y * W[6] + v.z * W[10] + v.w * W[14] + b[2];
    o.w = v.x * W[3] + v.y * W[7] + v.z * W[11] + v.w * W[15] + b[3];
    out[r] = o;
}

// ---------------- scatter (counting-sort finish) ----------------
__global__ void k_scatter_lg(const int* __restrict__ eilg) {
    int e = blockIdx.x * 256 + threadIdx.x;
    if (e >= ELG) return;
    int s = eilg[e];
    int d = eilg[ELG + e];
    int pos = atomicAdd(&g_cursor_lg[d], 1);
    g_src_sorted[pos] = s;
    g_nbg_sorted[pos] = g_nbg[s];
    g_ebg_sorted[pos] = g_ebg[e];
}
__global__ void k_scatter_g(const int* __restrict__ eig) {
    int e = blockIdx.x * 256 + threadIdx.x;
    if (e >= EG) return;
    int d = eig[EG + e];
    int pos = atomicAdd(&g_cursor_g[d], 1);
    g_eid_sorted[pos] = e;
}

// ---------------- node encoder: h_node = x_g @ W_enc + b_enc ----------------
__global__ void __launch_bounds__(256) k_enc(const float* __restrict__ xg,
                                             const float* __restrict__ Wenc,
                                             const float* __restrict__ benc) {
    __shared__ float xs[8][16];
    int t = threadIdx.x;
    int r0 = blockIdx.x * 8;
    if (t < 128) xs[t >> 4][t & 15] = xg[(r0 + (t >> 4)) * 16 + (t & 15)];
    __syncthreads();
    int f = t;
    float w[16];
    #pragma unroll
    for (int k = 0; k < 16; k++) w[k] = Wenc[k * HD + f];
    float b = benc[f];
    #pragma unroll
    for (int rr = 0; rr < 8; rr++) {
        float acc = b;
        #pragma unroll
        for (int k = 0; k < 16; k++) acc += xs[rr][k] * w[k];
        g_hnode[(size_t)(r0 + rr) * HD + f] = acc;
    }
}

// ---------------- generic fp32 SGEMM 128x128x8, 8x8 microtile ----------------
// A,C selected from device scratch; B/bias from inputs.
__global__ void __launch_bounds__(256) k_sgemm(
    const float* __restrict__ B, const float* __restrict__ bias,
    int M, int N, int K, int relu, int abuf, int cbuf, int addres)
{
    const float* A = (abuf == 0) ? g_hnode : (abuf == 1) ? g_hmid : g_mid2;
    float* C = (cbuf == 0) ? g_P : (cbuf == 1) ? g_Q : (cbuf == 2) ? g_mid2 : g_h;

    __shared__ float As[8][128];
    __shared__ float Bs[8][128];
    int tid = threadIdx.x;
    int bm = blockIdx.x * 128;
    int bn = blockIdx.y * 128;
    int tx = tid & 15, ty = tid >> 4;

    float acc[8][8];
    #pragma unroll
    for (int i = 0; i < 8; i++)
        #pragma unroll
        for (int j = 0; j < 8; j++) acc[i][j] = 0.f;

    int arow = tid >> 1;
    int akq  = (tid & 1) * 4;
    int brow = tid >> 5;
    int bcol = (tid & 31) * 4;
    const float* Ap = A + (size_t)(bm + arow) * K + akq;
    int avalid = (bm + arow) < M;
    const float* Bp = B + (size_t)brow * N + bn + bcol;

    for (int k0 = 0; k0 < K; k0 += 8) {
        float4 av = avalid ? *(const float4*)(Ap + k0) : make_float4(0.f, 0.f, 0.f, 0.f);
        As[akq + 0][arow] = av.x;
        As[akq + 1][arow] = av.y;
        As[akq + 2][arow] = av.z;
        As[akq + 3][arow] = av.w;
        float4 bvv = *(const float4*)(Bp + (size_t)k0 * N);
        *(float4*)&Bs[brow][bcol] = bvv;
        __syncthreads();
        #pragma unroll
        for (int kk = 0; kk < 8; kk++) {
            float ar[8], br[8];
            float4 t0 = *(const float4*)&As[kk][ty * 8];
            float4 t1 = *(const float4*)&As[kk][ty * 8 + 4];
            ar[0] = t0.x; ar[1] = t0.y; ar[2] = t0.z; ar[3] = t0.w;
            ar[4] = t1.x; ar[5] = t1.y; ar[6] = t1.z; ar[7] = t1.w;
            float4 u0 = *(const float4*)&Bs[kk][tx * 8];
            float4 u1 = *(const float4*)&Bs[kk][tx * 8 + 4];
            br[0] = u0.x; br[1] = u0.y; br[2] = u0.z; br[3] = u0.w;
            br[4] = u1.x; br[5] = u1.y; br[6] = u1.z; br[7] = u1.w;
            #pragma unroll
            for (int i = 0; i < 8; i++)
                #pragma unroll
                for (int j = 0; j < 8; j++) acc[i][j] += ar[i] * br[j];
        }
        __syncthreads();
    }

    int colb = bn + tx * 8;
    float4 bia0 = make_float4(0.f, 0.f, 0.f, 0.f), bia1 = bia0;
    if (bias) {
        bia0 = *(const float4*)&bias[colb];
        bia1 = *(const float4*)&bias[colb + 4];
    }
    #pragma unroll
    for (int i = 0; i < 8; i++) {
        int row = bm + ty * 8 + i;
        if (row < M) {
            float4 v0, v1;
            v0.x = acc[i][0] + bia0.x; v0.y = acc[i][1] + bia0.y;
            v0.z = acc[i][2] + bia0.z; v0.w = acc[i][3] + bia0.w;
            v1.x = acc[i][4] + bia1.x; v1.y = acc[i][5] + bia1.y;
            v1.z = acc[i][6] + bia1.z; v1.w = acc[i][7] + bia1.w;
            if (relu) {
                v0.x = fmaxf(v0.x, 0.f); v0.y = fmaxf(v0.y, 0.f);
                v0.z = fmaxf(v0.z, 0.f); v0.w = fmaxf(v0.w, 0.f);
                v1.x = fmaxf(v1.x, 0.f); v1.y = fmaxf(v1.y, 0.f);
                v1.z = fmaxf(v1.z, 0.f); v1.w = fmaxf(v1.w, 0.f);
            }
            if (addres) {
                float4 r0 = *(const float4*)&g_h[(size_t)row * N + colb];
                float4 r1 = *(const float4*)&g_h[(size_t)row * N + colb + 4];
                v0.x += r0.x; v0.y += r0.y; v0.z += r0.z; v0.w += r0.w;
                v1.x += r1.x; v1.y += r1.y; v1.z += r1.z; v1.w += r1.w;
            }
            *(float4*)&C[(size_t)row * N + colb] = v0;
            *(float4*)&C[(size_t)row * N + colb + 4] = v1;
        }
    }
}

// ---------------- first message embedding: h0 = P[src]+Q[dst]+ea@Wme+xlg@Wmx+b ----------------
__global__ void __launch_bounds__(256) k_h0(const float* __restrict__ ea,
                                            const float* __restrict__ xlg,
                                            const float* __restrict__ Wmsg,
                                            const float* __restrict__ bmsg,
                                            const int* __restrict__ eig) {
    __shared__ float sea[16][16];
    __shared__ float sxl[16][4];
    __shared__ int ssrc[16], sdst[16];
    int t = threadIdx.x;
    int e0 = blockIdx.x * 16;
    sea[t >> 4][t & 15] = ea[(size_t)e0 * 16 + t];
    if (t < 64) sxl[t >> 2][t & 3] = xlg[(size_t)e0 * 4 + t];
    if (t < 16) { ssrc[t] = eig[e0 + t]; sdst[t] = eig[EG + e0 + t]; }
    __syncthreads();
    int f = t;
    float wme[16];
    #pragma unroll
    for (int k = 0; k < 16; k++) wme[k] = Wmsg[(size_t)(512 + k) * HD + f];
    float wmx[4];
    #pragma unroll
    for (int k = 0; k < 4; k++) wmx[k] = Wmsg[(size_t)(528 + k) * HD + f];
    float bb = bmsg[f];
    #pragma unroll 1
    for (int ee = 0; ee < 16; ee++) {
        int e = e0 + ee;
        int s = ssrc[ee], d = sdst[ee];
        float acc = g_P[(size_t)s * HD + f] + g_Q[(size_t)d * HD + f] + bb;
        #pragma unroll
        for (int k = 0; k < 16; k++) acc += sea[ee][k] * wme[k];
        #pragma unroll
        for (int k = 0; k < 4; k++) acc += sxl[ee][k] * wmx[k];
        g_h[(size_t)e * HD + f] = acc;
    }
}

// ---------------- GENConv aggregation (online softmax, BN folded) ----------------
#define AGG_NPB 4
__global__ void __launch_bounds__(256) k_agg(const float* __restrict__ Wnb,
                                             const float* __restrict__ bnb,
                                             const float* __restrict__ Web,
                                             const float* __restrict__ beb,
                                             int use_bn) {
    int f = threadIdx.x;
    float w0 = Wnb[f], w1 = Wnb[HD + f], w2 = Wnb[2 * HD + f], w3 = Wnb[3 * HD + f];
    float e0 = Web[f], e1 = Web[HD + f], e2 = Web[2 * HD + f], e3 = Web[3 * HD + f];
    float cb = bnb[f] + beb[f];
    float sc = use_bn ? g_bnscale[f] : 1.f;
    float sh = use_bn ? g_bnshift[f] : 0.f;
    int d0 = blockIdx.x * AGG_NPB;
    const float NEG_INF = __int_as_float(0xff800000);
    #pragma unroll 1
    for (int dd = 0; dd < AGG_NPB; dd++) {
        int d = d0 + dd;
        int beg = g_rowptr_lg[d], end = g_rowptr_lg[d + 1];
        float xc = g_h[(size_t)d * HD + f];
        if (use_bn) xc = fmaxf(xc * sc + sh, 0.f);
        float M = NEG_INF, s = 0.f, w = 0.f;
        for (int p = beg; p < end; p++) {
            int srcn = g_src_sorted[p];
            float4 nb = g_nbg_sorted[p];
            float4 eb = g_ebg_sorted[p];
            float xv = g_h[(size_t)srcn * HD + f];
            if (use_bn) xv = fmaxf(xv * sc + sh, 0.f);
            float m = xv + nb.x * w0 + nb.y * w1 + nb.z * w2 + nb.w * w3
                         + eb.x * e0 + eb.y * e1 + eb.z * e2 + eb.w * e3 + cb;
            m = fmaxf(m, 0.f) + 1e-7f;
            float nM = fmaxf(M, m);
            float corr = __expf(M - nM);
            float ev = __expf(m - nM);
            s = s * corr + ev;
            w = w * corr + ev * m;
            M = nM;
        }
        float aggr = (end > beg) ? w / (s + 1e-16f) : 0.f;
        g_hmid[(size_t)d * HD + f] = xc + aggr;
    }
}

// ---------------- BatchNorm statistics (double accumulation) ----------------
__global__ void __launch_bounds__(256) k_bnstats() {
    int f = threadIdx.x;
    int r0 = blockIdx.x * 1000;
    double s = 0.0, q = 0.0;
    for (int rr = 0; rr < 1000; rr++) {
        float v = g_h[(size_t)(r0 + rr) * HD + f];
        s += (double)v;
        q += (double)v * (double)v;
    }
    atomicAdd(&g_bnsum[f], s);
    atomicAdd(&g_bnsq[f], q);
}

__global__ void k_bncoef(const float* __restrict__ gamma, const float* __restrict__ beta) {
    int f = threadIdx.x;
    double mean = g_bnsum[f] / (double)EG;
    double var = g_bnsq[f] / (double)EG - mean * mean;
    double r = 1.0 / sqrt(var + 1e-5);
    float scl = (float)((double)gamma[f] * r);
    g_bnscale[f] = scl;
    g_bnshift[f] = (float)((double)beta[f] - mean * (double)scl);
}

// ---------------- final: scatter to nodes (with final BN) + graph pooling ----------------
__global__ void __launch_bounds__(256) k_pool(const int* __restrict__ bv) {
    int f = threadIdx.x;
    float sc = g_bnscale[f], sh = g_bnshift[f];
    int n0 = blockIdx.x * 8;
    #pragma unroll 1
    for (int nn = 0; nn < 8; nn++) {
        int n = n0 + nn;
        int beg = g_rowptr_g[n], end = g_rowptr_g[n + 1];
        if (end > beg) {
            float acc = 0.f;
            for (int p = beg; p < end; p++) {
                int e = g_eid_sorted[p];
                acc += g_h[(size_t)e * HD + f] * sc + sh;
            }
            atomicAdd(&g_gsum[(size_t)bv[n] * HD + f], acc);
        }
    }
}

__global__ void k_pred(const float* __restrict__ Wpred, const float* __restrict__ bpred,
                       float* __restrict__ out) {
    __shared__ float red[256];
    int g = blockIdx.x;
    int f = threadIdx.x;
    float c = fmaxf((float)g_cnt[g], 1.0f);
    float v = (g_gsum[(size_t)g * HD + f] / c) * Wpred[f];
    red[f] = v;
    __syncthreads();
    for (int stw = 128; stw > 0; stw >>= 1) {
        if (f < stw) red[f] += red[f + stw];
        __syncthreads();
    }
    if (f == 0) out[g] = red[0] + bpred[0];
}

// ---------------- host ----------------
extern "C" void kernel_launch(void* const* d_in, const int* in_sizes, int n_in,
                              void* d_out, int out_size) {
    const float* xg    = (const float*)d_in[0];
    const float* ea    = (const float*)d_in[1];
    const float* xlg   = (const float*)d_in[2];
    const float* edb   = (const float*)d_in[3];
    const float* ealg  = (const float*)d_in[4];
    const float* Wenc  = (const float*)d_in[5];
    const float* benc  = (const float*)d_in[6];
    const float* Wmsg  = (const float*)d_in[7];
    const float* bmsg  = (const float*)d_in[8];
    const float* Wgnb  = (const float*)d_in[9];
    const float* bgnb  = (const float*)d_in[10];
    const float* Wgeb  = (const float*)d_in[11];
    const float* bgeb  = (const float*)d_in[12];
    const float* Wlnb  = (const float*)d_in[13];
    const float* blnb  = (const float*)d_in[14];
    const float* Wleb  = (const float*)d_in[15];
    const float* bleb  = (const float*)d_in[16];
    const float* W1    = (const float*)d_in[17];
    const float* b1    = (const float*)d_in[18];
    const float* W2    = (const float*)d_in[19];
    const float* b2    = (const float*)d_in[20];
    const float* gamma = (const float*)d_in[21];
    const float* beta  = (const float*)d_in[22];
    const float* Wpred = (const float*)d_in[23];
    const float* bpred = (const float*)d_in[24];
    const int*   eig   = (const int*)d_in[25];
    const int*   eilg  = (const int*)d_in[26];
    const int*   bv    = (const int*)d_in[27];
    float* out = (float*)d_out;

    // ---- setup: CSRs, basis projections, encoder, P/Q, h0 ----
    k_zero_setup<<<(EG + 255) / 256, 256>>>();
    k_hist_lg<<<(ELG + 255) / 256, 256>>>(eilg);
    k_hist_g<<<(EG + 255) / 256, 256>>>(eig);
    k_hist_batch<<<(NN + 255) / 256, 256>>>(bv);
    k_scan<<<1, 1024>>>(0);
    k_scan<<<1, 1024>>>(1);
    k_prepcur<<<(EG + 255) / 256, 256>>>();
    k_basis<<<(EG + 255) / 256, 256>>>(edb, Wgnb, bgnb, 0);
    k_basis<<<(ELG + 255) / 256, 256>>>(ealg, Wgeb, bgeb, 1);
    k_scatter_lg<<<(ELG + 255) / 256, 256>>>(eilg);
    k_scatter_g<<<(EG + 255) / 256, 256>>>(eig);
    k_enc<<<NN / 8, 256>>>(xg, Wenc, benc);

    dim3 gpq((NN + 127) / 128, HD / 128);
    k_sgemm<<<gpq, 256>>>(Wmsg,            nullptr, NN, HD, HD, 0, /*A=hnode*/0, /*C=P*/0, 0);
    k_sgemm<<<gpq, 256>>>(Wmsg + 256 * HD, nullptr, NN, HD, HD, 0, 0, /*C=Q*/1, 0);
    k_h0<<<EG / 16, 256>>>(ea, xlg, Wmsg, bmsg, eig);

    // ---- layers ----
    dim3 g1((EG + 127) / 128, HD2 / 128);
    dim3 g2((EG + 127) / 128, HD / 128);
    for (int l = 0; l < NL; l++) {
        if (l > 0) {
            k_zero_bn<<<1, 256>>>();
            k_bnstats<<<EG / 1000, 256>>>();
            k_bncoef<<<1, 256>>>(gamma + (l - 1) * HD, beta + (l - 1) * HD);
        }
        k_agg<<<EG / AGG_NPB, 256>>>(Wlnb + l * 4 * HD, blnb + l * HD,
                                     Wleb + l * 4 * HD, bleb + l * HD, l > 0);
        k_sgemm<<<g1, 256>>>(W1 + (size_t)l * HD * HD2, b1 + l * HD2,
                             EG, HD2, HD, /*relu*/1, /*A=hmid*/1, /*C=mid2*/2, 0);
        k_sgemm<<<g2, 256>>>(W2 + (size_t)l * HD2 * HD, b2 + l * HD,
                             EG, HD, HD2, /*relu*/0, /*A=mid2*/2, /*C=h*/3, /*res*/(l > 0) ? 1 : 0);
    }

    // ---- final BN + scatter-to-nodes + pooling + prediction ----
    k_zero_bn<<<1, 256>>>();
    k_bnstats<<<EG / 1000, 256>>>();
    k_bncoef<<<1, 256>>>(gamma + 3 * HD, beta + 3 * HD);
    k_pool<<<NN / 8, 256>>>(bv);
    k_pred<<<NG, 256>>>(Wpred, bpred, out);
}

// round 5
// speedup vs baseline: 1.7552x; 1.7552x over previous
#include <cuda_runtime.h>
#include <cuda_bf16.h>
#include <cstdint>

#define NN   20000
#define EG   200000
#define ELG  400000
#define HD   256
#define HD2  512
#define NL   4
#define NG   128
#define KS   40   // padded smem K stride (bf16 elems) -> 80B row stride, ldmatrix conflict-free

// ---------------- scratch (device globals; no allocations allowed) ----------------
__device__ float  g_hnode[NN * HD];
__device__ float  g_P[NN * HD];
__device__ float  g_Q[NN * HD];
__device__ float  g_h[EG * HD];        // current layer state (pre-BN)
__device__ float  g_hmid[EG * HD];     // x + aggr
__device__ float  g_mid2[EG * HD2];    // MLP hidden
__device__ float4 g_nbg[EG];
__device__ float4 g_ebg[ELG];
__device__ int    g_counts_lg[EG];
__device__ int    g_counts_g[NN];
__device__ int    g_rowptr_lg[EG + 1];
__device__ int    g_rowptr_g[NN + 1];
__device__ int    g_cursor_lg[EG];
__device__ int    g_cursor_g[NN];
__device__ int    g_src_sorted[ELG];
__device__ float4 g_nbg_sorted[ELG];
__device__ float4 g_ebg_sorted[ELG];
__device__ int    g_eid_sorted[EG];
__device__ double g_bnsum[HD];
__device__ double g_bnsq[HD];
__device__ float  g_bnscale[HD];
__device__ float  g_bnshift[HD];
__device__ float  g_gsum[NG * HD];
__device__ int    g_cnt[NG];

// weights converted to bf16 hi/lo, [N,K] K-contiguous
// layout: P(256x256) | Q(256x256) | W1 l=0..3 (512x256 each) | W2 l=0..3 (256x512 each)
#define WOFF_P  0
#define WOFF_Q  65536
#define WOFF_W1 131072              // + l*131072
#define WOFF_W2 655360              // + l*131072
#define WTOT    1179648
__device__ __nv_bfloat16 g_Wh[WTOT];
__device__ __nv_bfloat16 g_Wl[WTOT];

// ---------------- mma helpers (sm_80+ PTX, valid on sm_100 base) ----------------
__device__ __forceinline__ void ldsm4(uint32_t addr, uint32_t* r) {
    asm volatile("ldmatrix.sync.aligned.m8n8.x4.shared.b16 {%0,%1,%2,%3}, [%4];"
                 : "=r"(r[0]), "=r"(r[1]), "=r"(r[2]), "=r"(r[3]) : "r"(addr));
}
__device__ __forceinline__ void mma_bf16(float* c, const uint32_t* a, uint32_t b0, uint32_t b1) {
    asm volatile("mma.sync.aligned.m16n8k16.row.col.f32.bf16.bf16.f32 "
                 "{%0,%1,%2,%3}, {%4,%5,%6,%7}, {%8,%9}, {%0,%1,%2,%3};"
                 : "+f"(c[0]), "+f"(c[1]), "+f"(c[2]), "+f"(c[3])
                 : "r"(a[0]), "r"(a[1]), "r"(a[2]), "r"(a[3]), "r"(b0), "r"(b1));
}
__device__ __forceinline__ uint32_t smem_u32(const void* p) {
    uint32_t a;
    asm("{ .reg .u64 t; cvta.to.shared.u64 t, %1; cvt.u32.u64 %0, t; }" : "=r"(a) : "l"(p));
    return a;
}

// smem stage layout (bytes): A_hi 10240 | A_lo 10240 | B_hi 10240 | B_lo 10240
#define SA_HI 0
#define SA_LO 10240
#define SB_HI 20480
#define SB_LO 30720
#define STG   40960
#define MG_SMEM (2 * STG)

// ---------------- bf16x3 mma GEMM: C[M,N] = A[M,K] @ B[K,N] (+bias, relu, res) ----------------
// B pre-converted to [N,K] bf16 hi/lo at g_Wh/g_Wl + boff.
__global__ void __launch_bounds__(256, 1) k_mgemm(
    const float* __restrict__ bias,
    int M, int N, int K, int relu, int abuf, int cbuf, int addres, size_t boff)
{
    extern __shared__ char dsm[];
    const float* A = (abuf == 0) ? g_hnode : (abuf == 1) ? g_hmid : g_mid2;
    float* C = (cbuf == 0) ? g_P : (cbuf == 1) ? g_Q : (cbuf == 2) ? g_mid2 : g_h;
    const __nv_bfloat16* Bh = g_Wh + boff;
    const __nv_bfloat16* Bl = g_Wl + boff;

    int tid = threadIdx.x, wid = tid >> 5, lid = tid & 31;
    int bm = blockIdx.x * 128;
    int bn = blockIdx.y * 128;
    int mrows = M - bm; if (mrows > 128) mrows = 128;
    int wm = (wid >> 2) * 64;     // warp M offset in tile
    int wn = (wid & 3) * 32;      // warp N offset in tile

    // ---- global load staging assignments ----
    int arow = tid >> 1;                 // 0..127
    int acb  = (tid & 1) * 16;           // 0 or 16
    const float* Ap = A + (size_t)(bm + arow) * K + acb;
    bool aval = arow < mrows;

    // B: 512 uint4 per (hi|lo) array per chunk; thread t covers u = t and t+256
    int bu0 = tid, bu1 = tid + 256;
    int bn0 = bu0 >> 2, bq0 = bu0 & 3;
    int bn1 = bu1 >> 2, bq1 = bu1 & 3;
    const char* Bh0 = (const char*)(Bh + (size_t)(bn + bn0) * K + bq0 * 8);
    const char* Bh1 = (const char*)(Bh + (size_t)(bn + bn1) * K + bq1 * 8);
    const char* Bl0 = (const char*)(Bl + (size_t)(bn + bn0) * K + bq0 * 8);
    const char* Bl1 = (const char*)(Bl + (size_t)(bn + bn1) * K + bq1 * 8);

    // ---- ldmatrix per-lane offsets (bytes within array) ----
    int a_ml = (lid & 7) + ((lid >> 3) & 1) * 8;
    int a_kl = (lid >> 4) * 8;
    int b_nl = (lid & 7) + (lid >> 4) * 8;
    int b_kl = ((lid >> 3) & 1) * 8;
    uint32_t sbase = smem_u32(dsm);
    uint32_t aoff[4], boffm[2];
    #pragma unroll
    for (int mt = 0; mt < 4; mt++)
        aoff[mt] = (uint32_t)(((wm + mt * 16 + a_ml) * KS + a_kl) * 2);
    #pragma unroll
    for (int p = 0; p < 2; p++)
        boffm[p] = (uint32_t)(((wn + p * 16 + b_nl) * KS + b_kl) * 2);

    float acc[4][4][4];
    #pragma unroll
    for (int i = 0; i < 4; i++)
        #pragma unroll
        for (int j = 0; j < 4; j++)
            #pragma unroll
            for (int q = 0; q < 4; q++) acc[i][j][q] = 0.f;

    int nck = K >> 5;
    float aR[16];
    uint4 bhR[2], blR[2];

    // prologue: load chunk 0 into registers
    {
        if (aval) {
            #pragma unroll
            for (int i = 0; i < 4; i++) *(float4*)&aR[i * 4] = *(const float4*)(Ap + i * 4);
        } else {
            #pragma unroll
            for (int i = 0; i < 16; i++) aR[i] = 0.f;
        }
        bhR[0] = *(const uint4*)Bh0; bhR[1] = *(const uint4*)Bh1;
        blR[0] = *(const uint4*)Bl0; blR[1] = *(const uint4*)Bl1;
    }

    for (int c = 0; c < nck; c++) {
        int st = c & 1;
        char* sb = dsm + st * STG;
        // store A (convert to hi/lo)
        {
            __nv_bfloat16* ah = (__nv_bfloat16*)(sb + SA_HI) + arow * KS + acb;
            __nv_bfloat16* al = (__nv_bfloat16*)(sb + SA_LO) + arow * KS + acb;
            #pragma unroll
            for (int i = 0; i < 8; i++) {
                float x0 = aR[2 * i], x1 = aR[2 * i + 1];
                __nv_bfloat16 h0 = __float2bfloat16(x0);
                __nv_bfloat16 h1 = __float2bfloat16(x1);
                __nv_bfloat16 l0 = __float2bfloat16(x0 - __bfloat162float(h0));
                __nv_bfloat16 l1 = __float2bfloat16(x1 - __bfloat162float(h1));
                __nv_bfloat162 ph; ph.x = h0; ph.y = h1;
                __nv_bfloat162 pl; pl.x = l0; pl.y = l1;
                *(__nv_bfloat162*)(ah + 2 * i) = ph;
                *(__nv_bfloat162*)(al + 2 * i) = pl;
            }
        }
        // store B
        {
            *(uint4*)(sb + SB_HI + (bn0 * KS + bq0 * 8) * 2) = bhR[0];
            *(uint4*)(sb + SB_HI + (bn1 * KS + bq1 * 8) * 2) = bhR[1];
            *(uint4*)(sb + SB_LO + (bn0 * KS + bq0 * 8) * 2) = blR[0];
            *(uint4*)(sb + SB_LO + (bn1 * KS + bq1 * 8) * 2) = blR[1];
        }
        __syncthreads();
        // prefetch next chunk
        if (c + 1 < nck) {
            int co = (c + 1) * 32;
            if (aval) {
                #pragma unroll
                for (int i = 0; i < 4; i++) *(float4*)&aR[i * 4] = *(const float4*)(Ap + co + i * 4);
            }
            bhR[0] = *(const uint4*)(Bh0 + co * 2); bhR[1] = *(const uint4*)(Bh1 + co * 2);
            blR[0] = *(const uint4*)(Bl0 + co * 2); blR[1] = *(const uint4*)(Bl1 + co * 2);
        }
        // mma on this stage
        uint32_t stb = sbase + st * STG;
        #pragma unroll
        for (int kk = 0; kk < 2; kk++) {
            uint32_t ko = kk * 32;  // 16 bf16 = 32 bytes
            uint32_t ah[4][4], al[4][4], bh[2][4], bl[2][4];
            #pragma unroll
            for (int mt = 0; mt < 4; mt++) {
                ldsm4(stb + SA_HI + aoff[mt] + ko, ah[mt]);
                ldsm4(stb + SA_LO + aoff[mt] + ko, al[mt]);
            }
            #pragma unroll
            for (int p = 0; p < 2; p++) {
                ldsm4(stb + SB_HI + boffm[p] + ko, bh[p]);
                ldsm4(stb + SB_LO + boffm[p] + ko, bl[p]);
            }
            #pragma unroll
            for (int mt = 0; mt < 4; mt++) {
                #pragma unroll
                for (int nt = 0; nt < 4; nt++) {
                    int p = nt >> 1, o = (nt & 1) * 2;
                    mma_bf16(acc[mt][nt], ah[mt], bh[p][o], bh[p][o + 1]);
                    mma_bf16(acc[mt][nt], ah[mt], bl[p][o], bl[p][o + 1]);
                    mma_bf16(acc[mt][nt], al[mt], bh[p][o], bh[p][o + 1]);
                }
            }
        }
    }

    // ---- epilogue ----
    int l4 = lid >> 2, lc = (lid & 3) * 2;
    #pragma unroll
    for (int mt = 0; mt < 4; mt++) {
        #pragma unroll
        for (int nt = 0; nt < 4; nt++) {
            int m = bm + wm + mt * 16 + l4;
            int n = bn + wn + nt * 8 + lc;
            float2 bia = make_float2(0.f, 0.f);
            if (bias) bia = *(const float2*)&bias[n];
            #pragma unroll
            for (int half = 0; half < 2; half++) {
                int mm = m + half * 8;
                if (mm < M) {
                    float v0 = acc[mt][nt][half * 2 + 0] + bia.x;
                    float v1 = acc[mt][nt][half * 2 + 1] + bia.y;
                    if (relu) { v0 = fmaxf(v0, 0.f); v1 = fmaxf(v1, 0.f); }
                    if (addres) {
                        float2 rr = *(const float2*)&g_h[(size_t)mm * N + n];
                        v0 += rr.x; v1 += rr.y;
                    }
                    float2 ov; ov.x = v0; ov.y = v1;
                    *(float2*)&C[(size_t)mm * N + n] = ov;
                }
            }
        }
    }
}

// ---------------- weight transpose + bf16 hi/lo split: in[K,N] -> g_Wh/g_Wl[N,K] ----------------
__global__ void k_wconv(const float* __restrict__ in, int K, int N, size_t off) {
    __shared__ float t[32][33];
    int k0 = blockIdx.x * 32, n0 = blockIdx.y * 32;
    int x = threadIdx.x, y = threadIdx.y;
    for (int i = y; i < 32; i += 8) t[i][x] = in[(size_t)(k0 + i) * N + n0 + x];
    __syncthreads();
    for (int i = y; i < 32; i += 8) {
        float v = t[x][i];
        __nv_bfloat16 h = __float2bfloat16(v);
        __nv_bfloat16 lo = __float2bfloat16(v - __bfloat162float(h));
        size_t o = off + (size_t)(n0 + i) * K + k0 + x;
        g_Wh[o] = h;
        g_Wl[o] = lo;
    }
}

// ---------------- setup / zero ----------------
__global__ void k_zero_setup() {
    int i = blockIdx.x * 256 + threadIdx.x;
    if (i < EG)       g_counts_lg[i] = 0;
    if (i < NN)       g_counts_g[i] = 0;
    if (i < NG * HD)  g_gsum[i] = 0.f;
    if (i < NG)       g_cnt[i] = 0;
}

__global__ void k_zero_bn() {
    int f = threadIdx.x;
    g_bnsum[f] = 0.0;
    g_bnsq[f] = 0.0;
}

// ---------------- histograms ----------------
__global__ void k_hist_lg(const int* __restrict__ eilg) {
    int e = blockIdx.x * 256 + threadIdx.x;
    if (e < ELG) atomicAdd(&g_counts_lg[eilg[ELG + e]], 1);
}
__global__ void k_hist_g(const int* __restrict__ eig) {
    int e = blockIdx.x * 256 + threadIdx.x;
    if (e < EG) atomicAdd(&g_counts_g[eig[EG + e]], 1);
}
__global__ void k_hist_batch(const int* __restrict__ bv) {
    int n = blockIdx.x * 256 + threadIdx.x;
    if (n < NN) atomicAdd(&g_cnt[bv[n]], 1);
}

// ---------------- exclusive scan (single block, 1024 threads) ----------------
__global__ void k_scan(int which) {
    const int* in;
    int* out;
    int n;
    if (which == 0) { in = g_counts_lg; out = g_rowptr_lg; n = EG; }
    else            { in = g_counts_g;  out = g_rowptr_g;  n = NN; }
    __shared__ int sd[1024];
    int t = threadIdx.x;
    int carry = 0;
    for (int base = 0; base < n; base += 1024) {
        int v = (base + t < n) ? in[base + t] : 0;
        sd[t] = v;
        __syncthreads();
        #pragma unroll
        for (int off = 1; off < 1024; off <<= 1) {
            int x = (t >= off) ? sd[t - off] : 0;
            __syncthreads();
            sd[t] += x;
            __syncthreads();
        }
        int incl = sd[t];
        int tot = sd[1023];
        if (base + t < n) out[base + t] = carry + incl - v;
        carry += tot;
        __syncthreads();
    }
    if (t == 0) out[n] = carry;
}

__global__ void k_prepcur() {
    int i = blockIdx.x * 256 + threadIdx.x;
    if (i < EG) g_cursor_lg[i] = g_rowptr_lg[i];
    if (i < NN) g_cursor_g[i] = g_rowptr_g[i];
}

// ---------------- tiny 4->4 basis projections ----------------
__global__ void k_basis(const float* __restrict__ in, const float* __restrict__ W,
                        const float* __restrict__ b, int which) {
    int R = (which == 0) ? EG : ELG;
    float4* out = (which == 0) ? g_nbg : g_ebg;
    int r = blockIdx.x * 256 + threadIdx.x;
    if (r >= R) return;
    float4 v = ((const float4*)in)[r];
    float4 o;
    o.x = v.x * W[0] + v.y * W[4] + v.z * W[8]  + v.w * W[12] + b[0];
    o.y = v.x * W[1] + v.y * W[5] + v.z * W[9]  + v.w * W[13] + b[1];
    o.z = v.x * W[2] + v.y * W[6] + v.z * W[10] + v.w * W[14] + b[2];
    o.w = v.x * W[3] + v.y * W[7] + v.z * W[11] + v.w * W[15] + b[3];
    out[r] = o;
}

// ---------------- scatter (counting-sort finish) ----------------
__global__ void k_scatter_lg(const int* __restrict__ eilg) {
    int e = blockIdx.x * 256 + threadIdx.x;
    if (e >= ELG) return;
    int s = eilg[e];
    int d = eilg[ELG + e];
    int pos = atomicAdd(&g_cursor_lg[d], 1);
    g_src_sorted[pos] = s;
    g_nbg_sorted[pos] = g_nbg[s];
    g_ebg_sorted[pos] = g_ebg[e];
}
__global__ void k_scatter_g(const int* __restrict__ eig) {
    int e = blockIdx.x * 256 + threadIdx.x;
    if (e >= EG) return;
    int d = eig[EG + e];
    int pos = atomicAdd(&g_cursor_g[d], 1);
    g_eid_sorted[pos] = e;
}

// ---------------- node encoder: h_node = x_g @ W_enc + b_enc ----------------
__global__ void __launch_bounds__(256) k_enc(const float* __restrict__ xg,
                                             const float* __restrict__ Wenc,
                                             const float* __restrict__ benc) {
    __shared__ float xs[8][16];
    int t = threadIdx.x;
    int r0 = blockIdx.x * 8;
    if (t < 128) xs[t >> 4][t & 15] = xg[(r0 + (t >> 4)) * 16 + (t & 15)];
    __syncthreads();
    int f = t;
    float w[16];
    #pragma unroll
    for (int k = 0; k < 16; k++) w[k] = Wenc[k * HD + f];
    float b = benc[f];
    #pragma unroll
    for (int rr = 0; rr < 8; rr++) {
        float acc = b;
        #pragma unroll
        for (int k = 0; k < 16; k++) acc += xs[rr][k] * w[k];
        g_hnode[(size_t)(r0 + rr) * HD + f] = acc;
    }
}

// ---------------- first message embedding ----------------
__global__ void __launch_bounds__(256) k_h0(const float* __restrict__ ea,
                                            const float* __restrict__ xlg,
                                            const float* __restrict__ Wmsg,
                                            const float* __restrict__ bmsg,
                                            const int* __restrict__ eig) {
    __shared__ float sea[16][16];
    __shared__ float sxl[16][4];
    __shared__ int ssrc[16], sdst[16];
    int t = threadIdx.x;
    int e0 = blockIdx.x * 16;
    sea[t >> 4][t & 15] = ea[(size_t)e0 * 16 + t];
    if (t < 64) sxl[t >> 2][t & 3] = xlg[(size_t)e0 * 4 + t];
    if (t < 16) { ssrc[t] = eig[e0 + t]; sdst[t] = eig[EG + e0 + t]; }
    __syncthreads();
    int f = t;
    float wme[16];
    #pragma unroll
    for (int k = 0; k < 16; k++) wme[k] = Wmsg[(size_t)(512 + k) * HD + f];
    float wmx[4];
    #pragma unroll
    for (int k = 0; k < 4; k++) wmx[k] = Wmsg[(size_t)(528 + k) * HD + f];
    float bb = bmsg[f];
    #pragma unroll 1
    for (int ee = 0; ee < 16; ee++) {
        int e = e0 + ee;
        int s = ssrc[ee], d = sdst[ee];
        float acc = g_P[(size_t)s * HD + f] + g_Q[(size_t)d * HD + f] + bb;
        #pragma unroll
        for (int k = 0; k < 16; k++) acc += sea[ee][k] * wme[k];
        #pragma unroll
        for (int k = 0; k < 4; k++) acc += sxl[ee][k] * wmx[k];
        g_h[(size_t)e * HD + f] = acc;
    }
}

// ---------------- GENConv aggregation (online softmax, BN folded) ----------------
#define AGG_NPB 4
__global__ void __launch_bounds__(256) k_agg(const float* __restrict__ Wnb,
                                             const float* __restrict__ bnb,
                                             const float* __restrict__ Web,
                                             const float* __restrict__ beb,
                                             int use_bn) {
    int f = threadIdx.x;
    float w0 = Wnb[f], w1 = Wnb[HD + f], w2 = Wnb[2 * HD + f], w3 = Wnb[3 * HD + f];
    float e0 = Web[f], e1 = Web[HD + f], e2 = Web[2 * HD + f], e3 = Web[3 * HD + f];
    float cb = bnb[f] + beb[f];
    float sc = use_bn ? g_bnscale[f] : 1.f;
    float sh = use_bn ? g_bnshift[f] : 0.f;
    int d0 = blockIdx.x * AGG_NPB;
    const float NEG_INF = __int_as_float(0xff800000);
    #pragma unroll 1
    for (int dd = 0; dd < AGG_NPB; dd++) {
        int d = d0 + dd;
        int beg = g_rowptr_lg[d], end = g_rowptr_lg[d + 1];
        float xc = g_h[(size_t)d * HD + f];
        if (use_bn) xc = fmaxf(xc * sc + sh, 0.f);
        float M = NEG_INF, s = 0.f, w = 0.f;
        for (int p = beg; p < end; p++) {
            int srcn = g_src_sorted[p];
            float4 nb = g_nbg_sorted[p];
            float4 eb = g_ebg_sorted[p];
            float xv = g_h[(size_t)srcn * HD + f];
            if (use_bn) xv = fmaxf(xv * sc + sh, 0.f);
            float m = xv + nb.x * w0 + nb.y * w1 + nb.z * w2 + nb.w * w3
                         + eb.x * e0 + eb.y * e1 + eb.z * e2 + eb.w * e3 + cb;
            m = fmaxf(m, 0.f) + 1e-7f;
            float nM = fmaxf(M, m);
            float corr = __expf(M - nM);
            float ev = __expf(m - nM);
            s = s * corr + ev;
            w = w * corr + ev * m;
            M = nM;
        }
        float aggr = (end > beg) ? w / (s + 1e-16f) : 0.f;
        g_hmid[(size_t)d * HD + f] = xc + aggr;
    }
}

// ---------------- BatchNorm statistics (double accumulation) ----------------
__global__ void __launch_bounds__(256) k_bnstats() {
    int f = threadIdx.x;
    int r0 = blockIdx.x * 1000;
    double s = 0.0, q = 0.0;
    for (int rr = 0; rr < 1000; rr++) {
        float v = g_h[(size_t)(r0 + rr) * HD + f];
        s += (double)v;
        q += (double)v * (double)v;
    }
    atomicAdd(&g_bnsum[f], s);
    atomicAdd(&g_bnsq[f], q);
}

__global__ void k_bncoef(const float* __restrict__ gamma, const float* __restrict__ beta) {
    int f = threadIdx.x;
    double mean = g_bnsum[f] / (double)EG;
    double var = g_bnsq[f] / (double)EG - mean * mean;
    double r = 1.0 / sqrt(var + 1e-5);
    float scl = (float)((double)gamma[f] * r);
    g_bnscale[f] = scl;
    g_bnshift[f] = (float)((double)beta[f] - mean * (double)scl);
}

// ---------------- final: scatter to nodes (with final BN) + graph pooling ----------------
__global__ void __launch_bounds__(256) k_pool(const int* __restrict__ bv) {
    int f = threadIdx.x;
    float sc = g_bnscale[f], sh = g_bnshift[f];
    int n0 = blockIdx.x * 8;
    #pragma unroll 1
    for (int nn = 0; nn < 8; nn++) {
        int n = n0 + nn;
        int beg = g_rowptr_g[n], end = g_rowptr_g[n + 1];
        if (end > beg) {
            float acc = 0.f;
            for (int p = beg; p < end; p++) {
                int e = g_eid_sorted[p];
                acc += g_h[(size_t)e * HD + f] * sc + sh;
            }
            atomicAdd(&g_gsum[(size_t)bv[n] * HD + f], acc);
        }
    }
}

__global__ void k_pred(const float* __restrict__ Wpred, const float* __restrict__ bpred,
                       float* __restrict__ out) {
    __shared__ float red[256];
    int g = blockIdx.x;
    int f = threadIdx.x;
    float c = fmaxf((float)g_cnt[g], 1.0f);
    float v = (g_gsum[(size_t)g * HD + f] / c) * Wpred[f];
    red[f] = v;
    __syncthreads();
    for (int stw = 128; stw > 0; stw >>= 1) {
        if (f < stw) red[f] += red[f + stw];
        __syncthreads();
    }
    if (f == 0) out[g] = red[0] + bpred[0];
}

// ---------------- host ----------------
extern "C" void kernel_launch(void* const* d_in, const int* in_sizes, int n_in,
                              void* d_out, int out_size) {
    const float* xg    = (const float*)d_in[0];
    const float* ea    = (const float*)d_in[1];
    const float* xlg   = (const float*)d_in[2];
    const float* edb   = (const float*)d_in[3];
    const float* ealg  = (const float*)d_in[4];
    const float* Wenc  = (const float*)d_in[5];
    const float* benc  = (const float*)d_in[6];
    const float* Wmsg  = (const float*)d_in[7];
    const float* bmsg  = (const float*)d_in[8];
    const float* Wgnb  = (const float*)d_in[9];
    const float* bgnb  = (const float*)d_in[10];
    const float* Wgeb  = (const float*)d_in[11];
    const float* bgeb  = (const float*)d_in[12];
    const float* Wlnb  = (const float*)d_in[13];
    const float* blnb  = (const float*)d_in[14];
    const float* Wleb  = (const float*)d_in[15];
    const float* bleb  = (const float*)d_in[16];
    const float* W1    = (const float*)d_in[17];
    const float* b1    = (const float*)d_in[18];
    const float* W2    = (const float*)d_in[19];
    const float* b2    = (const float*)d_in[20];
    const float* gamma = (const float*)d_in[21];
    const float* beta  = (const float*)d_in[22];
    const float* Wpred = (const float*)d_in[23];
    const float* bpred = (const float*)d_in[24];
    const int*   eig   = (const int*)d_in[25];
    const int*   eilg  = (const int*)d_in[26];
    const int*   bv    = (const int*)d_in[27];
    float* out = (float*)d_out;

    cudaFuncSetAttribute(k_mgemm, cudaFuncAttributeMaxDynamicSharedMemorySize, MG_SMEM);

    // ---- weight conversion (transpose to [N,K] + bf16 hi/lo split) ----
    dim3 tb(32, 8);
    k_wconv<<<dim3(8, 8), tb>>>(Wmsg,            HD,  HD,  WOFF_P);
    k_wconv<<<dim3(8, 8), tb>>>(Wmsg + HD * HD,  HD,  HD,  WOFF_Q);
    for (int l = 0; l < NL; l++) {
        k_wconv<<<dim3(8, 16), tb>>>(W1 + (size_t)l * HD * HD2, HD,  HD2, WOFF_W1 + (size_t)l * 131072);
        k_wconv<<<dim3(16, 8), tb>>>(W2 + (size_t)l * HD2 * HD, HD2, HD,  WOFF_W2 + (size_t)l * 131072);
    }

    // ---- setup: CSRs, basis projections, encoder ----
    k_zero_setup<<<(EG + 255) / 256, 256>>>();
    k_hist_lg<<<(ELG + 255) / 256, 256>>>(eilg);
    k_hist_g<<<(EG + 255) / 256, 256>>>(eig);
    k_hist_batch<<<(NN + 255) / 256, 256>>>(bv);
    k_scan<<<1, 1024>>>(0);
    k_scan<<<1, 1024>>>(1);
    k_prepcur<<<(EG + 255) / 256, 256>>>();
    k_basis<<<(EG + 255) / 256, 256>>>(edb, Wgnb, bgnb, 0);
    k_basis<<<(ELG + 255) / 256, 256>>>(ealg, Wgeb, bgeb, 1);
    k_scatter_lg<<<(ELG + 255) / 256, 256>>>(eilg);
    k_scatter_g<<<(EG + 255) / 256, 256>>>(eig);
    k_enc<<<NN / 8, 256>>>(xg, Wenc, benc);

    // ---- P/Q node GEMMs + first message embedding ----
    int gpq = (NN + 127) / 128;
    k_mgemm<<<dim3(gpq, HD / 128), 256, MG_SMEM>>>(nullptr, NN, HD, HD, 0, /*A=hnode*/0, /*C=P*/0, 0, WOFF_P);
    k_mgemm<<<dim3(gpq, HD / 128), 256, MG_SMEM>>>(nullptr, NN, HD, HD, 0, 0, /*C=Q*/1, 0, WOFF_Q);
    k_h0<<<EG / 16, 256>>>(ea, xlg, Wmsg, bmsg, eig);

    // ---- layers ----
    int gE = (EG + 127) / 128;
    for (int l = 0; l < NL; l++) {
        if (l > 0) {
            k_zero_bn<<<1, 256>>>();
            k_bnstats<<<EG / 1000, 256>>>();
            k_bncoef<<<1, 256>>>(gamma + (l - 1) * HD, beta + (l - 1) * HD);
        }
        k_agg<<<EG / AGG_NPB, 256>>>(Wlnb + l * 4 * HD, blnb + l * HD,
                                     Wleb + l * 4 * HD, bleb + l * HD, l > 0);
        k_mgemm<<<dim3(gE, HD2 / 128), 256, MG_SMEM>>>(b1 + l * HD2, EG, HD2, HD, /*relu*/1,
                                                       /*A=hmid*/1, /*C=mid2*/2, 0,
                                                       WOFF_W1 + (size_t)l * 131072);
        k_mgemm<<<dim3(gE, HD / 128), 256, MG_SMEM>>>(b2 + l * HD, EG, HD, HD2, /*relu*/0,
                                                      /*A=mid2*/2, /*C=h*/3, /*res*/(l > 0) ? 1 : 0,
                                                      WOFF_W2 + (size_t)l * 131072);
    }

    // ---- final BN + scatter-to-nodes + pooling + prediction ----
    k_zero_bn<<<1, 256>>>();
    k_bnstats<<<EG / 1000, 256>>>();
    k_bncoef<<<1, 256>>>(gamma + 3 * HD, beta + 3 * HD);
    k_pool<<<NN / 8, 256>>>(bv);
    k_pred<<<NG, 256>>>(Wpred, bpred, out);
}